// round 11
// baseline (speedup 1.0000x reference)
#include <cuda_runtime.h>

#define NB 2
#define NC 64
#define D  64
#define NVOX (D*D*D)            // 262144
#define NCH  (NB*NC)            // 128
#define TOT  (NCH*NVOX)         // 33554432

#define FIX_T   0.02f
#define MAXFIX  (1<<22)

#define PSTR 65                 // padded smem row stride (float2 elems)
#define ZPB  8                  // z-planes per box_wh block

// Scratch (no cudaMalloc allowed)
__device__ float2 g_p [TOT];    // (qk, qkv) bit-exact proj output (fixup source)
__device__ float2 g_t2[TOT];    // after w+h passes
__device__ float2 g_stage[NC*NC];  // staging for packed (wq,wk), [l][c]
__device__ int    g_cnt;
__device__ int    g_fixlist[MAXFIX];

// Weights in constant memory: separate cache port, warp-uniform accesses.
__constant__ float2 cQK[NC*NC];    // [l][c] (wq, wk)  32 KB
__constant__ float  cV [NC*NC];    // [l][c] wv        16 KB

__global__ void reset_kernel() { g_cnt = 0; }
__global__ void noop_kernel() {}

// Pack (wq,wk) interleaved in [l][c] order into staging (then D2D -> cQK).
__global__ __launch_bounds__(256) void wpack_kernel(
    const float* __restrict__ qw, const float* __restrict__ kw)
{
    const int i = blockIdx.x * 256 + threadIdx.x;   // i = l*64 + c
    g_stage[i] = make_float2(qw[i], kw[i]);
}

// ---------------------------------------------------------------------------
// Stage 1: per-voxel projections — R8's measured-387us kernel with weights
// moved from shared memory to __constant__ (same values, same FMA sequence ->
// bit-identical g_p; load-bearing for near-zero denominators, see fixup).
// aq/ak: one packed fma.rn.f32x2 chain (each lane IEEE fp32, ascending c);
// av: scalar FFMA chain. qk = q*k; qkv = qk*v single roundings.
// No smem, no block barrier; weight reads hit the constant port (uniform).
// ---------------------------------------------------------------------------
__global__ __launch_bounds__(128) void proj_kernel(
    const float* __restrict__ mov, const float* __restrict__ fix)
{
    const int tid = threadIdx.x;
    const int gid = blockIdx.x * 128 + tid;     // 0 .. NB*NVOX-1
    const int b   = (gid >= NVOX) ? 1 : 0;
    const int n   = gid - b * NVOX;

    const float* mp = mov + (long)b*NC*NVOX + n;
    const float* fp = fix + (long)b*NC*NVOX + n;

    unsigned long long mf[NC];   // packed (m[c], f[c])
    float f[NC];
    #pragma unroll
    for (int c = 0; c < NC; c++) {
        const float mv = mp[(long)c*NVOX];
        const float fv = fp[(long)c*NVOX];
        f[c] = fv;
        asm("mov.b64 %0, {%1,%2};" : "=l"(mf[c]) : "f"(mv), "f"(fv));
    }

    float2* op = g_p + (long)b*NC*NVOX + n;

    for (int l = 0; l < NC; l++) {
        const ulonglong2* wrow = (const ulonglong2*)(cQK + (l<<6));
        const float4*     vrow = (const float4*)(cV + (l<<6));
        unsigned long long aqk = 0ull;   // lanes: (aq, ak)
        float av = 0.f;
        #pragma unroll
        for (int j = 0; j < NC/4; j++) {
            const ulonglong2 wa = wrow[2*j];      // c = 4j, 4j+1
            const ulonglong2 wb = wrow[2*j+1];    // c = 4j+2, 4j+3
            const float4 wv4 = vrow[j];
            asm("fma.rn.f32x2 %0, %1, %2, %0;" : "+l"(aqk) : "l"(wa.x), "l"(mf[4*j+0]));
            av = __fmaf_rn(wv4.x, f[4*j+0], av);
            asm("fma.rn.f32x2 %0, %1, %2, %0;" : "+l"(aqk) : "l"(wa.y), "l"(mf[4*j+1]));
            av = __fmaf_rn(wv4.y, f[4*j+1], av);
            asm("fma.rn.f32x2 %0, %1, %2, %0;" : "+l"(aqk) : "l"(wb.x), "l"(mf[4*j+2]));
            av = __fmaf_rn(wv4.z, f[4*j+2], av);
            asm("fma.rn.f32x2 %0, %1, %2, %0;" : "+l"(aqk) : "l"(wb.y), "l"(mf[4*j+3]));
            av = __fmaf_rn(wv4.w, f[4*j+3], av);
        }
        float aq, ak;
        asm("mov.b64 {%0,%1}, %2;" : "=f"(aq), "=f"(ak) : "l"(aqk));
        const float qk  = __fmul_rn(aq, ak);
        const float qkv = __fmul_rn(qk, av);
        op[(long)l*NVOX] = make_float2(qk, qkv);
    }
}

// ---------------------------------------------------------------------------
// Stage 2ab (fused, software-pipelined): W then H box sums (R9, measured 112us).
// ---------------------------------------------------------------------------
__global__ __launch_bounds__(256) void box_wh_kernel()
{
    extern __shared__ float2 smp[];
    float2* P = smp;               // [64][PSTR] current input plane
    float2* Q = smp + D*PSTR;      // [64][PSTR] after w-pass

    const int tid  = threadIdx.x;
    const int z0   = blockIdx.x * ZPB;
    const int chan = blockIdx.y;
    const long cb  = (long)chan*NVOX;

    for (int i = tid; i < D*D; i += 256)
        P[(i >> 6)*PSTR + (i & 63)] = g_p[cb + (long)z0*(D*D) + i];
    __syncthreads();

    #pragma unroll 1
    for (int p = 0; p < ZPB; p++) {
        const long nb = cb + (long)(z0 + p + 1)*(D*D);
        const bool pf = (p + 1 < ZPB);
        float2 rA[8], rB[8];

        if (pf) {
            #pragma unroll
            for (int k = 0; k < 8; k++) rA[k] = g_p[nb + k*256 + tid];
        }

        // w-pass: P -> Q
        {
            const int h   = tid & 63;
            const int w0  = (tid >> 6) * 16;
            const float2* row = P + h*PSTR;
            float2* qrow = Q + h*PSTR;
            float sx = 0.f, sy = 0.f;
            const int j0 = (w0 >= 4) ? (w0 - 4) : 0;
            for (int j = j0; j < w0 + 4; j++) { sx += row[j].x; sy += row[j].y; }
            #pragma unroll
            for (int i = 0; i < 16; i++) {
                const int w = w0 + i;
                if (w + 4 < D) { sx += row[w+4].x; sy += row[w+4].y; }
                qrow[w] = make_float2(sx, sy);
                if (w >= 4) { sx -= row[w-4].x; sy -= row[w-4].y; }
            }
        }
        __syncthreads();

        if (pf) {
            #pragma unroll
            for (int k = 0; k < 8; k++) rB[k] = g_p[nb + (k+8)*256 + tid];
        }

        // h-pass: Q -> g_t2
        {
            const int w   = tid & 63;
            const int h0  = (tid >> 6) * 16;
            const long pbase = cb + (long)(z0 + p)*(D*D);
            float sx = 0.f, sy = 0.f;
            const int j0 = (h0 >= 4) ? (h0 - 4) : 0;
            for (int j = j0; j < h0 + 4; j++) {
                const float2 v = Q[j*PSTR + w];
                sx += v.x; sy += v.y;
            }
            #pragma unroll
            for (int i = 0; i < 16; i++) {
                const int h = h0 + i;
                if (h + 4 < D) {
                    const float2 v = Q[(h+4)*PSTR + w];
                    sx += v.x; sy += v.y;
                }
                g_t2[pbase + h*D + w] = make_float2(sx, sy);
                if (h >= 4) {
                    const float2 v = Q[(h-4)*PSTR + w];
                    sx -= v.x; sy -= v.y;
                }
            }
        }

        if (pf) {
            #pragma unroll
            for (int k = 0; k < 8; k++) {
                const int i = k*256 + tid;
                P[(i >> 6)*PSTR + (i & 63)] = rA[k];
            }
            #pragma unroll
            for (int k = 0; k < 8; k++) {
                const int i = (k+8)*256 + tid;
                P[(i >> 6)*PSTR + (i & 63)] = rB[k];
            }
        }
        __syncthreads();
    }
}

// ---------------------------------------------------------------------------
// Stage 2c: box sum along Z + division; flag near-zero denominators.
// ---------------------------------------------------------------------------
__global__ __launch_bounds__(256) void box_z_div_kernel(float* __restrict__ out)
{
    const int t    = threadIdx.x;
    const int wp   = t & 31;
    const int h    = blockIdx.x * 8 + (t >> 5);
    const int chan = blockIdx.y;
    const long ebase = (long)chan*NVOX + (long)h*D + 2*wp;
    const long base  = ebase >> 1;
    const float4* src = (const float4*)g_t2;
    float2*       o2  = (float2*)out;

    float4 ring[9];
    float4 s = make_float4(0.f, 0.f, 0.f, 0.f);
    #pragma unroll
    for (int j = 0; j < 4; j++) {
        float4 v = src[base + (long)j*(D*D/2)];
        ring[j % 9] = v;
        s.x += v.x; s.y += v.y; s.z += v.z; s.w += v.w;
    }
    #pragma unroll
    for (int i = 0; i < D; i++) {
        const int j = i + 4;
        if (j < D) {
            float4 v = src[base + (long)j*(D*D/2)];
            ring[j % 9] = v;
            s.x += v.x; s.y += v.y; s.z += v.z; s.w += v.w;
        }
        const long eidx = ebase + (long)i*(D*D);
        o2[eidx >> 1] = make_float2(__fdiv_rn(s.y, s.x), __fdiv_rn(s.w, s.z));
        if (fabsf(s.x) < FIX_T) {
            int slot = atomicAdd(&g_cnt, 1);
            if (slot < MAXFIX) g_fixlist[slot] = (int)eidx;
        }
        if (fabsf(s.z) < FIX_T) {
            int slot = atomicAdd(&g_cnt, 1);
            if (slot < MAXFIX) g_fixlist[slot] = (int)(eidx + 1);
        }
        const int j2 = i - 4;
        if (j2 >= 0) {
            float4 v = ring[j2 % 9];
            s.x -= v.x; s.y -= v.y; s.z -= v.z; s.w -= v.w;
        }
    }
}

// ---------------------------------------------------------------------------
// Stage 3: exact fixup — reference's sequential in-bounds 729-tap fold
// (ascending z,h,w; fp32 adds; init 0) over the bit-exact g_p field.
// ---------------------------------------------------------------------------
__global__ __launch_bounds__(256) void fixup_kernel(float* __restrict__ out)
{
    int cnt = g_cnt; if (cnt > MAXFIX) cnt = MAXFIX;
    for (int idx = blockIdx.x*256 + threadIdx.x; idx < cnt; idx += gridDim.x*256) {
        const int v    = g_fixlist[idx];
        const int chan = v >> 18;
        const int rem  = v & (NVOX-1);
        const int z = rem >> 12;
        const int h = (rem >> 6) & 63;
        const int w = rem & 63;
        const long cb = (long)chan*NVOX;

        const int zlo = z-4 < 0 ? 0 : z-4, zhi = z+4 > 63 ? 63 : z+4;
        const int hlo = h-4 < 0 ? 0 : h-4, hhi = h+4 > 63 ? 63 : h+4;
        const int wlo = w-4 < 0 ? 0 : w-4, whi = w+4 > 63 ? 63 : w+4;

        float sD = 0.f, sN = 0.f;
        for (int dz = zlo; dz <= zhi; dz++)
            for (int dh = hlo; dh <= hhi; dh++) {
                const float2* row = g_p + cb + ((long)dz*D + dh)*D;
                for (int dw = wlo; dw <= whi; dw++) {
                    float2 x = row[dw];
                    sD = __fadd_rn(sD, x.x);
                    sN = __fadd_rn(sN, x.y);
                }
            }
        out[v] = __fdiv_rn(sN, sD);
    }
}

extern "C" void kernel_launch(void* const* d_in, const int* in_sizes, int n_in,
                              void* d_out, int out_size) {
    (void)in_sizes; (void)n_in; (void)out_size;
    const float* mov = (const float*)d_in[0];
    const float* fix = (const float*)d_in[1];
    const float* qw  = (const float*)d_in[2];
    const float* kw  = (const float*)d_in[3];
    const float* vw  = (const float*)d_in[4];
    float* out = (float*)d_out;

    const int wh_smem = 2*D*PSTR * sizeof(float2);      // 66560 B
    cudaFuncSetAttribute(box_wh_kernel,
                         cudaFuncAttributeMaxDynamicSharedMemorySize, wh_smem);

    void* stage_ptr = 0;
    cudaGetSymbolAddress(&stage_ptr, g_stage);

    reset_kernel<<<1, 1>>>();                                  // 0
    wpack_kernel<<<16, 256>>>(qw, kw);                         // 1
    cudaMemcpyToSymbolAsync(cQK, stage_ptr, NC*NC*sizeof(float2), 0,
                            cudaMemcpyDeviceToDevice);
    cudaMemcpyToSymbolAsync(cV, vw, NC*NC*sizeof(float), 0,
                            cudaMemcpyDeviceToDevice);
    noop_kernel<<<1, 32>>>();                                  // 2
    proj_kernel<<<(NB*NVOX)/128, 128>>>(mov, fix);             // 3 (captured)
    box_wh_kernel<<<dim3(D/ZPB, NCH), 256, wh_smem>>>();
    box_z_div_kernel<<<dim3(8, NCH), 256>>>(out);
    fixup_kernel<<<512, 256>>>(out);
}

// round 12
// speedup vs baseline: 1.3369x; 1.3369x over previous
#include <cuda_runtime.h>

#define NB 2
#define NC 64
#define D  64
#define NVOX (D*D*D)            // 262144
#define NCH  (NB*NC)            // 128
#define TOT  (NCH*NVOX)         // 33554432

#define FIX_T   0.02f
#define MAXFIX  (1<<22)

#define PSTR 65                 // padded smem row stride (float2 elems)
#define ZPB  8                  // z-planes per box_wh block

// Scratch (no cudaMalloc allowed)
__device__ float2 g_p [TOT];    // (qk, qkv) bit-exact proj output (fixup source)
__device__ float2 g_t2[TOT];    // after w+h passes
__device__ int    g_cnt;
__device__ int    g_fixlist[MAXFIX];

__global__ void reset_kernel() { g_cnt = 0; }
__global__ void noop_kernel() {}

// ---------------------------------------------------------------------------
// Stage 1: per-voxel projections. 128-thread blocks (R8-proven geometry).
// Live state = mf[64] packed (m,f) pairs ONLY (~155 regs -> zero spill).
// Two packed fma.rn.f32x2 chains per l (each lane an IEEE fp32 FMA):
//   acc1 lanes (aq, ak) += (wq, wk) · (m, f)
//   acc2 lanes (xx, av) += (wv, wv) · (m, f)   -> lane1 is the exact
//                                                 sequential av chain
// All three logical chains are bit-identical to scalar sequential ascending-c
// chains (validated R5/R6). qk = q*k; qkv = qk*v single roundings.
// g_p bit-exactness is load-bearing for near-zero denominators (fixup).
// No barriers after smem weight fill.
// ---------------------------------------------------------------------------
__global__ __launch_bounds__(128) void proj_kernel(
    const float* __restrict__ mov, const float* __restrict__ fix,
    const float* __restrict__ qw,  const float* __restrict__ kw,
    const float* __restrict__ vw)
{
    __shared__ float2 swqk[NC*NC];   // [l][c] (wq, wk)  32 KB
    __shared__ float2 swv2[NC*NC];   // [l][c] (wv, wv)  32 KB
    const int tid = threadIdx.x;
    for (int i = tid; i < NC*NC; i += 128) {
        swqk[i] = make_float2(qw[i], kw[i]);
        const float v = vw[i];
        swv2[i] = make_float2(v, v);
    }
    __syncthreads();

    const int gid = blockIdx.x * 128 + tid;     // 0 .. NB*NVOX-1
    const int b   = (gid >= NVOX) ? 1 : 0;
    const int n   = gid - b * NVOX;

    const float* mp = mov + (long)b*NC*NVOX + n;
    const float* fp = fix + (long)b*NC*NVOX + n;

    unsigned long long mf[NC];   // packed (m[c], f[c]) — the ONLY big live array
    #pragma unroll
    for (int c = 0; c < NC; c++) {
        const float mv = mp[(long)c*NVOX];
        const float fv = fp[(long)c*NVOX];
        asm("mov.b64 %0, {%1,%2};" : "=l"(mf[c]) : "f"(mv), "f"(fv));
    }

    float2* op = g_p + (long)b*NC*NVOX + n;

    #pragma unroll 1
    for (int l = 0; l < NC; l++) {
        const ulonglong2* wrow = (const ulonglong2*)(swqk + (l<<6));
        const ulonglong2* vrow = (const ulonglong2*)(swv2 + (l<<6));
        unsigned long long aqk = 0ull;   // lanes (aq, ak)
        unsigned long long avv = 0ull;   // lanes (xx, av)
        #pragma unroll
        for (int j = 0; j < NC/4; j++) {
            const ulonglong2 wa = wrow[2*j];      // c = 4j, 4j+1
            const ulonglong2 wb = wrow[2*j+1];    // c = 4j+2, 4j+3
            const ulonglong2 va = vrow[2*j];
            const ulonglong2 vb = vrow[2*j+1];
            asm("fma.rn.f32x2 %0, %1, %2, %0;" : "+l"(aqk) : "l"(wa.x), "l"(mf[4*j+0]));
            asm("fma.rn.f32x2 %0, %1, %2, %0;" : "+l"(avv) : "l"(va.x), "l"(mf[4*j+0]));
            asm("fma.rn.f32x2 %0, %1, %2, %0;" : "+l"(aqk) : "l"(wa.y), "l"(mf[4*j+1]));
            asm("fma.rn.f32x2 %0, %1, %2, %0;" : "+l"(avv) : "l"(va.y), "l"(mf[4*j+1]));
            asm("fma.rn.f32x2 %0, %1, %2, %0;" : "+l"(aqk) : "l"(wb.x), "l"(mf[4*j+2]));
            asm("fma.rn.f32x2 %0, %1, %2, %0;" : "+l"(avv) : "l"(vb.x), "l"(mf[4*j+2]));
            asm("fma.rn.f32x2 %0, %1, %2, %0;" : "+l"(aqk) : "l"(wb.y), "l"(mf[4*j+3]));
            asm("fma.rn.f32x2 %0, %1, %2, %0;" : "+l"(avv) : "l"(vb.y), "l"(mf[4*j+3]));
        }
        float aq, ak, xx, av;
        asm("mov.b64 {%0,%1}, %2;" : "=f"(aq), "=f"(ak) : "l"(aqk));
        asm("mov.b64 {%0,%1}, %2;" : "=f"(xx), "=f"(av) : "l"(avv));
        const float qk  = __fmul_rn(aq, ak);
        const float qkv = __fmul_rn(qk, av);
        op[(long)l*NVOX] = make_float2(qk, qkv);
    }
}

// ---------------------------------------------------------------------------
// Stage 2ab (fused, software-pipelined): W then H box sums (R9, measured 112us).
// ---------------------------------------------------------------------------
__global__ __launch_bounds__(256) void box_wh_kernel()
{
    extern __shared__ float2 smp[];
    float2* P = smp;               // [64][PSTR] current input plane
    float2* Q = smp + D*PSTR;      // [64][PSTR] after w-pass

    const int tid  = threadIdx.x;
    const int z0   = blockIdx.x * ZPB;
    const int chan = blockIdx.y;
    const long cb  = (long)chan*NVOX;

    for (int i = tid; i < D*D; i += 256)
        P[(i >> 6)*PSTR + (i & 63)] = g_p[cb + (long)z0*(D*D) + i];
    __syncthreads();

    #pragma unroll 1
    for (int p = 0; p < ZPB; p++) {
        const long nb = cb + (long)(z0 + p + 1)*(D*D);
        const bool pf = (p + 1 < ZPB);
        float2 rA[8], rB[8];

        if (pf) {
            #pragma unroll
            for (int k = 0; k < 8; k++) rA[k] = g_p[nb + k*256 + tid];
        }

        // w-pass: P -> Q
        {
            const int h   = tid & 63;
            const int w0  = (tid >> 6) * 16;
            const float2* row = P + h*PSTR;
            float2* qrow = Q + h*PSTR;
            float sx = 0.f, sy = 0.f;
            const int j0 = (w0 >= 4) ? (w0 - 4) : 0;
            for (int j = j0; j < w0 + 4; j++) { sx += row[j].x; sy += row[j].y; }
            #pragma unroll
            for (int i = 0; i < 16; i++) {
                const int w = w0 + i;
                if (w + 4 < D) { sx += row[w+4].x; sy += row[w+4].y; }
                qrow[w] = make_float2(sx, sy);
                if (w >= 4) { sx -= row[w-4].x; sy -= row[w-4].y; }
            }
        }
        __syncthreads();

        if (pf) {
            #pragma unroll
            for (int k = 0; k < 8; k++) rB[k] = g_p[nb + (k+8)*256 + tid];
        }

        // h-pass: Q -> g_t2
        {
            const int w   = tid & 63;
            const int h0  = (tid >> 6) * 16;
            const long pbase = cb + (long)(z0 + p)*(D*D);
            float sx = 0.f, sy = 0.f;
            const int j0 = (h0 >= 4) ? (h0 - 4) : 0;
            for (int j = j0; j < h0 + 4; j++) {
                const float2 v = Q[j*PSTR + w];
                sx += v.x; sy += v.y;
            }
            #pragma unroll
            for (int i = 0; i < 16; i++) {
                const int h = h0 + i;
                if (h + 4 < D) {
                    const float2 v = Q[(h+4)*PSTR + w];
                    sx += v.x; sy += v.y;
                }
                g_t2[pbase + h*D + w] = make_float2(sx, sy);
                if (h >= 4) {
                    const float2 v = Q[(h-4)*PSTR + w];
                    sx -= v.x; sy -= v.y;
                }
            }
        }

        if (pf) {
            #pragma unroll
            for (int k = 0; k < 8; k++) {
                const int i = k*256 + tid;
                P[(i >> 6)*PSTR + (i & 63)] = rA[k];
            }
            #pragma unroll
            for (int k = 0; k < 8; k++) {
                const int i = (k+8)*256 + tid;
                P[(i >> 6)*PSTR + (i & 63)] = rB[k];
            }
        }
        __syncthreads();
    }
}

// ---------------------------------------------------------------------------
// Stage 2c: box sum along Z + division; flag near-zero denominators.
// ---------------------------------------------------------------------------
__global__ __launch_bounds__(256) void box_z_div_kernel(float* __restrict__ out)
{
    const int t    = threadIdx.x;
    const int wp   = t & 31;
    const int h    = blockIdx.x * 8 + (t >> 5);
    const int chan = blockIdx.y;
    const long ebase = (long)chan*NVOX + (long)h*D + 2*wp;
    const long base  = ebase >> 1;
    const float4* src = (const float4*)g_t2;
    float2*       o2  = (float2*)out;

    float4 ring[9];
    float4 s = make_float4(0.f, 0.f, 0.f, 0.f);
    #pragma unroll
    for (int j = 0; j < 4; j++) {
        float4 v = src[base + (long)j*(D*D/2)];
        ring[j % 9] = v;
        s.x += v.x; s.y += v.y; s.z += v.z; s.w += v.w;
    }
    #pragma unroll
    for (int i = 0; i < D; i++) {
        const int j = i + 4;
        if (j < D) {
            float4 v = src[base + (long)j*(D*D/2)];
            ring[j % 9] = v;
            s.x += v.x; s.y += v.y; s.z += v.z; s.w += v.w;
        }
        const long eidx = ebase + (long)i*(D*D);
        o2[eidx >> 1] = make_float2(__fdiv_rn(s.y, s.x), __fdiv_rn(s.w, s.z));
        if (fabsf(s.x) < FIX_T) {
            int slot = atomicAdd(&g_cnt, 1);
            if (slot < MAXFIX) g_fixlist[slot] = (int)eidx;
        }
        if (fabsf(s.z) < FIX_T) {
            int slot = atomicAdd(&g_cnt, 1);
            if (slot < MAXFIX) g_fixlist[slot] = (int)(eidx + 1);
        }
        const int j2 = i - 4;
        if (j2 >= 0) {
            float4 v = ring[j2 % 9];
            s.x -= v.x; s.y -= v.y; s.z -= v.z; s.w -= v.w;
        }
    }
}

// ---------------------------------------------------------------------------
// Stage 3: exact fixup — reference's sequential in-bounds 729-tap fold
// (ascending z,h,w; fp32 adds; init 0) over the bit-exact g_p field.
// ---------------------------------------------------------------------------
__global__ __launch_bounds__(256) void fixup_kernel(float* __restrict__ out)
{
    int cnt = g_cnt; if (cnt > MAXFIX) cnt = MAXFIX;
    for (int idx = blockIdx.x*256 + threadIdx.x; idx < cnt; idx += gridDim.x*256) {
        const int v    = g_fixlist[idx];
        const int chan = v >> 18;
        const int rem  = v & (NVOX-1);
        const int z = rem >> 12;
        const int h = (rem >> 6) & 63;
        const int w = rem & 63;
        const long cb = (long)chan*NVOX;

        const int zlo = z-4 < 0 ? 0 : z-4, zhi = z+4 > 63 ? 63 : z+4;
        const int hlo = h-4 < 0 ? 0 : h-4, hhi = h+4 > 63 ? 63 : h+4;
        const int wlo = w-4 < 0 ? 0 : w-4, whi = w+4 > 63 ? 63 : w+4;

        float sD = 0.f, sN = 0.f;
        for (int dz = zlo; dz <= zhi; dz++)
            for (int dh = hlo; dh <= hhi; dh++) {
                const float2* row = g_p + cb + ((long)dz*D + dh)*D;
                for (int dw = wlo; dw <= whi; dw++) {
                    float2 x = row[dw];
                    sD = __fadd_rn(sD, x.x);
                    sN = __fadd_rn(sN, x.y);
                }
            }
        out[v] = __fdiv_rn(sN, sD);
    }
}

extern "C" void kernel_launch(void* const* d_in, const int* in_sizes, int n_in,
                              void* d_out, int out_size) {
    (void)in_sizes; (void)n_in; (void)out_size;
    const float* mov = (const float*)d_in[0];
    const float* fix = (const float*)d_in[1];
    const float* qw  = (const float*)d_in[2];
    const float* kw  = (const float*)d_in[3];
    const float* vw  = (const float*)d_in[4];
    float* out = (float*)d_out;

    const int wh_smem = 2*D*PSTR * sizeof(float2);      // 66560 B
    cudaFuncSetAttribute(box_wh_kernel,
                         cudaFuncAttributeMaxDynamicSharedMemorySize, wh_smem);

    reset_kernel<<<1, 1>>>();                           // 0
    noop_kernel<<<1, 32>>>();                           // 1
    noop_kernel<<<1, 32>>>();                           // 2
    proj_kernel<<<(NB*NVOX)/128, 128>>>(mov, fix, qw, kw, vw);   // 3 (captured)
    box_wh_kernel<<<dim3(D/ZPB, NCH), 256, wh_smem>>>();
    box_z_div_kernel<<<dim3(8, NCH), 256>>>(out);
    fixup_kernel<<<512, 256>>>(out);
}

// round 13
// speedup vs baseline: 1.4417x; 1.0784x over previous
#include <cuda_runtime.h>

#define NB 2
#define NC 64
#define D  64
#define NVOX (D*D*D)            // 262144
#define NCH  (NB*NC)            // 128
#define TOT  (NCH*NVOX)         // 33554432

#define FIX_T   0.02f
#define MAXFIX  (1<<22)

#define PSTR 65                 // padded smem row stride (float2 elems)
#define ZPB  8                  // z-planes per box_wh block

#define GRID_P 304              // persistent proj blocks (2 per SM)
#define NT     (NB*NVOX/64)     // 8192 voxel tiles of 64

// Scratch (no cudaMalloc allowed)
__device__ float2 g_p [TOT];    // (qk, qkv) bit-exact proj output (fixup source)
__device__ float2 g_t2[TOT];    // after w+h passes
__device__ int    g_cnt;
__device__ int    g_fixlist[MAXFIX];

__global__ void reset_kernel() { g_cnt = 0; }
__global__ void noop_kernel() {}

// ---------------------------------------------------------------------------
// Stage 1: persistent register-tiled projection GEMM.
// Block (256 thr) loads all weights to smem ONCE, then loops over 64-voxel
// tiles (strided by grid). Thread computes 4 l x 4 vox. Per (l,vox):
//   aqk lanes (aq,ak): single fma.rn.f32x2 chain over ascending c with
//                      weights (wq,wk) and operand (m,f)
//   av lanes (vox even, vox odd): chain with (wv,wv) and (f,f') pairs
// Each lane is an IEEE fp32 FMA -> all chains bit-identical to the validated
// scalar sequential ascending-c chains. qk=q*k, qkv=qk*v single roundings.
// g_p bit-exactness is load-bearing for near-zero denominators (fixup).
// Next tile's (m,f) prefetched to registers during compute (R9 pattern).
// ---------------------------------------------------------------------------
__global__ __launch_bounds__(256, 2) void proj_kernel(
    const float* __restrict__ mov, const float* __restrict__ fix,
    const float* __restrict__ qw,  const float* __restrict__ kw,
    const float* __restrict__ vw)
{
    extern __shared__ float psm[];
    float2* sWQK = (float2*)psm;              // [c][l] (wq,wk)  32 KB
    float*  sWV  = (float*)(sWQK + NC*NC);    // [c][l] wv       16 KB
    float2* sMF  = (float2*)(sWV + NC*NC);    // [c][vox] (m,f)  32 KB
    float*  sFv  = (float*)(sMF + NC*NC);     // [c][vox] f      16 KB

    const int tid = threadIdx.x;

    // one-time transposed weight load [l][c] -> [c][l]
    for (int i = tid; i < NC*NC; i += 256) {
        const int c = i >> 6, l = i & 63;
        sWQK[i] = make_float2(qw[l*NC + c], kw[l*NC + c]);
        sWV[i]  = vw[l*NC + c];
    }

    const int l0 = (tid >> 4) << 2;     // 16 l-teams x 4
    const int v0 = (tid & 15) << 2;     // 16 vox-teams x 4

    float4 rm[4], rf[4];
    // preload first tile to regs
    {
        const int t = blockIdx.x;
        const int gv0 = t << 6;
        const int b = (gv0 >= NVOX) ? 1 : 0;
        const int n0 = gv0 & (NVOX - 1);
        const float* bm = mov + (long)b*NC*NVOX + n0;
        const float* bf = fix + (long)b*NC*NVOX + n0;
        #pragma unroll
        for (int k = 0; k < 4; k++) {
            const int idx = tid + (k << 8);
            const int c = idx >> 4, vg = idx & 15;
            rm[k] = *(const float4*)(bm + (long)c*NVOX + vg*4);
            rf[k] = *(const float4*)(bf + (long)c*NVOX + vg*4);
        }
    }
    // commit first tile to smem
    #pragma unroll
    for (int k = 0; k < 4; k++) {
        const int idx = tid + (k << 8);
        float2* d = sMF + idx*4;
        d[0] = make_float2(rm[k].x, rf[k].x);
        d[1] = make_float2(rm[k].y, rf[k].y);
        d[2] = make_float2(rm[k].z, rf[k].z);
        d[3] = make_float2(rm[k].w, rf[k].w);
        *(float4*)(sFv + idx*4) = rf[k];
    }
    __syncthreads();

    #pragma unroll 1
    for (int t = blockIdx.x; t < NT; t += GRID_P) {
        const int tn = t + GRID_P;
        // prefetch next tile into regs (overlaps compute)
        if (tn < NT) {
            const int gv0 = tn << 6;
            const int b = (gv0 >= NVOX) ? 1 : 0;
            const int n0 = gv0 & (NVOX - 1);
            const float* bm = mov + (long)b*NC*NVOX + n0;
            const float* bf = fix + (long)b*NC*NVOX + n0;
            #pragma unroll
            for (int k = 0; k < 4; k++) {
                const int idx = tid + (k << 8);
                const int c = idx >> 4, vg = idx & 15;
                rm[k] = *(const float4*)(bm + (long)c*NVOX + vg*4);
                rf[k] = *(const float4*)(bf + (long)c*NVOX + vg*4);
            }
        }

        // ---- compute current tile ----
        unsigned long long aqk[4][4];   // lanes (aq, ak)
        unsigned long long av [4][2];   // lanes (av_v2p, av_v2p+1)
        #pragma unroll
        for (int li = 0; li < 4; li++) {
            #pragma unroll
            for (int vi = 0; vi < 4; vi++) aqk[li][vi] = 0ull;
            av[li][0] = 0ull; av[li][1] = 0ull;
        }

        #pragma unroll 2
        for (int c = 0; c < NC; c++) {
            const ulonglong2* wp = (const ulonglong2*)(sWQK + c*NC + l0);
            const ulonglong2 w01 = wp[0], w23 = wp[1];
            const float4 wv4 = *(const float4*)(sWV + c*NC + l0);
            const ulonglong2* mp2 = (const ulonglong2*)(sMF + c*NC + v0);
            const ulonglong2 mfa = mp2[0], mfb = mp2[1];   // (mf_v0,mf_v1),(mf_v2,mf_v3)
            const ulonglong2 fp2 = *(const ulonglong2*)(sFv + c*NC + v0); // (f0,f1),(f2,f3)

            unsigned long long vv[4];
            asm("mov.b64 %0, {%1,%1};" : "=l"(vv[0]) : "f"(wv4.x));
            asm("mov.b64 %0, {%1,%1};" : "=l"(vv[1]) : "f"(wv4.y));
            asm("mov.b64 %0, {%1,%1};" : "=l"(vv[2]) : "f"(wv4.z));
            asm("mov.b64 %0, {%1,%1};" : "=l"(vv[3]) : "f"(wv4.w));
            const unsigned long long wl[4] = {w01.x, w01.y, w23.x, w23.y};
            const unsigned long long mf4[4] = {mfa.x, mfa.y, mfb.x, mfb.y};

            #pragma unroll
            for (int li = 0; li < 4; li++) {
                asm("fma.rn.f32x2 %0, %1, %2, %0;" : "+l"(aqk[li][0]) : "l"(wl[li]), "l"(mf4[0]));
                asm("fma.rn.f32x2 %0, %1, %2, %0;" : "+l"(aqk[li][1]) : "l"(wl[li]), "l"(mf4[1]));
                asm("fma.rn.f32x2 %0, %1, %2, %0;" : "+l"(aqk[li][2]) : "l"(wl[li]), "l"(mf4[2]));
                asm("fma.rn.f32x2 %0, %1, %2, %0;" : "+l"(aqk[li][3]) : "l"(wl[li]), "l"(mf4[3]));
                asm("fma.rn.f32x2 %0, %1, %2, %0;" : "+l"(av[li][0]) : "l"(vv[li]), "l"(fp2.x));
                asm("fma.rn.f32x2 %0, %1, %2, %0;" : "+l"(av[li][1]) : "l"(vv[li]), "l"(fp2.y));
            }
        }

        // epilogue + store
        {
            const int gv0 = t << 6;
            const int b = (gv0 >= NVOX) ? 1 : 0;
            const int n0 = gv0 & (NVOX - 1);
            #pragma unroll
            for (int li = 0; li < 4; li++) {
                float r[8];
                #pragma unroll
                for (int vi = 0; vi < 4; vi++) {
                    float aq, ak, a0, a1;
                    asm("mov.b64 {%0,%1}, %2;" : "=f"(aq), "=f"(ak) : "l"(aqk[li][vi]));
                    asm("mov.b64 {%0,%1}, %2;" : "=f"(a0), "=f"(a1) : "l"(av[li][vi>>1]));
                    const float avv = (vi & 1) ? a1 : a0;
                    const float qk  = __fmul_rn(aq, ak);
                    const float qkv = __fmul_rn(qk, avv);
                    r[2*vi]   = qk;
                    r[2*vi+1] = qkv;
                }
                float4* po = (float4*)(g_p + (long)b*NC*NVOX + (long)(l0+li)*NVOX + n0 + v0);
                po[0] = make_float4(r[0], r[1], r[2], r[3]);
                po[1] = make_float4(r[4], r[5], r[6], r[7]);
            }
        }
        __syncthreads();     // all smem reads of tile t done

        // commit prefetched tile to smem
        if (tn < NT) {
            #pragma unroll
            for (int k = 0; k < 4; k++) {
                const int idx = tid + (k << 8);
                float2* d = sMF + idx*4;
                d[0] = make_float2(rm[k].x, rf[k].x);
                d[1] = make_float2(rm[k].y, rf[k].y);
                d[2] = make_float2(rm[k].z, rf[k].z);
                d[3] = make_float2(rm[k].w, rf[k].w);
                *(float4*)(sFv + idx*4) = rf[k];
            }
        }
        __syncthreads();     // next tile ready
    }
}

// ---------------------------------------------------------------------------
// Stage 2ab (fused, software-pipelined): W then H box sums (R9, measured 112us).
// ---------------------------------------------------------------------------
__global__ __launch_bounds__(256) void box_wh_kernel()
{
    extern __shared__ float2 smp[];
    float2* P = smp;               // [64][PSTR] current input plane
    float2* Q = smp + D*PSTR;      // [64][PSTR] after w-pass

    const int tid  = threadIdx.x;
    const int z0   = blockIdx.x * ZPB;
    const int chan = blockIdx.y;
    const long cb  = (long)chan*NVOX;

    for (int i = tid; i < D*D; i += 256)
        P[(i >> 6)*PSTR + (i & 63)] = g_p[cb + (long)z0*(D*D) + i];
    __syncthreads();

    #pragma unroll 1
    for (int p = 0; p < ZPB; p++) {
        const long nb = cb + (long)(z0 + p + 1)*(D*D);
        const bool pf = (p + 1 < ZPB);
        float2 rA[8], rB[8];

        if (pf) {
            #pragma unroll
            for (int k = 0; k < 8; k++) rA[k] = g_p[nb + k*256 + tid];
        }

        // w-pass: P -> Q
        {
            const int h   = tid & 63;
            const int w0  = (tid >> 6) * 16;
            const float2* row = P + h*PSTR;
            float2* qrow = Q + h*PSTR;
            float sx = 0.f, sy = 0.f;
            const int j0 = (w0 >= 4) ? (w0 - 4) : 0;
            for (int j = j0; j < w0 + 4; j++) { sx += row[j].x; sy += row[j].y; }
            #pragma unroll
            for (int i = 0; i < 16; i++) {
                const int w = w0 + i;
                if (w + 4 < D) { sx += row[w+4].x; sy += row[w+4].y; }
                qrow[w] = make_float2(sx, sy);
                if (w >= 4) { sx -= row[w-4].x; sy -= row[w-4].y; }
            }
        }
        __syncthreads();

        if (pf) {
            #pragma unroll
            for (int k = 0; k < 8; k++) rB[k] = g_p[nb + (k+8)*256 + tid];
        }

        // h-pass: Q -> g_t2
        {
            const int w   = tid & 63;
            const int h0  = (tid >> 6) * 16;
            const long pbase = cb + (long)(z0 + p)*(D*D);
            float sx = 0.f, sy = 0.f;
            const int j0 = (h0 >= 4) ? (h0 - 4) : 0;
            for (int j = j0; j < h0 + 4; j++) {
                const float2 v = Q[j*PSTR + w];
                sx += v.x; sy += v.y;
            }
            #pragma unroll
            for (int i = 0; i < 16; i++) {
                const int h = h0 + i;
                if (h + 4 < D) {
                    const float2 v = Q[(h+4)*PSTR + w];
                    sx += v.x; sy += v.y;
                }
                g_t2[pbase + h*D + w] = make_float2(sx, sy);
                if (h >= 4) {
                    const float2 v = Q[(h-4)*PSTR + w];
                    sx -= v.x; sy -= v.y;
                }
            }
        }

        if (pf) {
            #pragma unroll
            for (int k = 0; k < 8; k++) {
                const int i = k*256 + tid;
                P[(i >> 6)*PSTR + (i & 63)] = rA[k];
            }
            #pragma unroll
            for (int k = 0; k < 8; k++) {
                const int i = (k+8)*256 + tid;
                P[(i >> 6)*PSTR + (i & 63)] = rB[k];
            }
        }
        __syncthreads();
    }
}

// ---------------------------------------------------------------------------
// Stage 2c: box sum along Z + division; flag near-zero denominators.
// ---------------------------------------------------------------------------
__global__ __launch_bounds__(256) void box_z_div_kernel(float* __restrict__ out)
{
    const int t    = threadIdx.x;
    const int wp   = t & 31;
    const int h    = blockIdx.x * 8 + (t >> 5);
    const int chan = blockIdx.y;
    const long ebase = (long)chan*NVOX + (long)h*D + 2*wp;
    const long base  = ebase >> 1;
    const float4* src = (const float4*)g_t2;
    float2*       o2  = (float2*)out;

    float4 ring[9];
    float4 s = make_float4(0.f, 0.f, 0.f, 0.f);
    #pragma unroll
    for (int j = 0; j < 4; j++) {
        float4 v = src[base + (long)j*(D*D/2)];
        ring[j % 9] = v;
        s.x += v.x; s.y += v.y; s.z += v.z; s.w += v.w;
    }
    #pragma unroll
    for (int i = 0; i < D; i++) {
        const int j = i + 4;
        if (j < D) {
            float4 v = src[base + (long)j*(D*D/2)];
            ring[j % 9] = v;
            s.x += v.x; s.y += v.y; s.z += v.z; s.w += v.w;
        }
        const long eidx = ebase + (long)i*(D*D);
        o2[eidx >> 1] = make_float2(__fdiv_rn(s.y, s.x), __fdiv_rn(s.w, s.z));
        if (fabsf(s.x) < FIX_T) {
            int slot = atomicAdd(&g_cnt, 1);
            if (slot < MAXFIX) g_fixlist[slot] = (int)eidx;
        }
        if (fabsf(s.z) < FIX_T) {
            int slot = atomicAdd(&g_cnt, 1);
            if (slot < MAXFIX) g_fixlist[slot] = (int)(eidx + 1);
        }
        const int j2 = i - 4;
        if (j2 >= 0) {
            float4 v = ring[j2 % 9];
            s.x -= v.x; s.y -= v.y; s.z -= v.z; s.w -= v.w;
        }
    }
}

// ---------------------------------------------------------------------------
// Stage 3: exact fixup — reference's sequential in-bounds 729-tap fold
// (ascending z,h,w; fp32 adds; init 0) over the bit-exact g_p field.
// ---------------------------------------------------------------------------
__global__ __launch_bounds__(256) void fixup_kernel(float* __restrict__ out)
{
    int cnt = g_cnt; if (cnt > MAXFIX) cnt = MAXFIX;
    for (int idx = blockIdx.x*256 + threadIdx.x; idx < cnt; idx += gridDim.x*256) {
        const int v    = g_fixlist[idx];
        const int chan = v >> 18;
        const int rem  = v & (NVOX-1);
        const int z = rem >> 12;
        const int h = (rem >> 6) & 63;
        const int w = rem & 63;
        const long cb = (long)chan*NVOX;

        const int zlo = z-4 < 0 ? 0 : z-4, zhi = z+4 > 63 ? 63 : z+4;
        const int hlo = h-4 < 0 ? 0 : h-4, hhi = h+4 > 63 ? 63 : h+4;
        const int wlo = w-4 < 0 ? 0 : w-4, whi = w+4 > 63 ? 63 : w+4;

        float sD = 0.f, sN = 0.f;
        for (int dz = zlo; dz <= zhi; dz++)
            for (int dh = hlo; dh <= hhi; dh++) {
                const float2* row = g_p + cb + ((long)dz*D + dh)*D;
                for (int dw = wlo; dw <= whi; dw++) {
                    float2 x = row[dw];
                    sD = __fadd_rn(sD, x.x);
                    sN = __fadd_rn(sN, x.y);
                }
            }
        out[v] = __fdiv_rn(sN, sD);
    }
}

extern "C" void kernel_launch(void* const* d_in, const int* in_sizes, int n_in,
                              void* d_out, int out_size) {
    (void)in_sizes; (void)n_in; (void)out_size;
    const float* mov = (const float*)d_in[0];
    const float* fix = (const float*)d_in[1];
    const float* qw  = (const float*)d_in[2];
    const float* kw  = (const float*)d_in[3];
    const float* vw  = (const float*)d_in[4];
    float* out = (float*)d_out;

    const int proj_smem = 98304;                        // 96 KB
    const int wh_smem   = 2*D*PSTR * sizeof(float2);    // 66560 B
    cudaFuncSetAttribute(proj_kernel,
                         cudaFuncAttributeMaxDynamicSharedMemorySize, proj_smem);
    cudaFuncSetAttribute(box_wh_kernel,
                         cudaFuncAttributeMaxDynamicSharedMemorySize, wh_smem);

    reset_kernel<<<1, 1>>>();                           // 0
    noop_kernel<<<1, 32>>>();                           // 1
    noop_kernel<<<1, 32>>>();                           // 2
    proj_kernel<<<GRID_P, 256, proj_smem>>>(mov, fix, qw, kw, vw);   // 3 (captured)
    box_wh_kernel<<<dim3(D/ZPB, NCH), 256, wh_smem>>>();
    box_z_div_kernel<<<dim3(8, NCH), 256>>>(out);
    fixup_kernel<<<512, 256>>>(out);
}

// round 14
// speedup vs baseline: 1.4521x; 1.0072x over previous
#include <cuda_runtime.h>

#define NB 2
#define NC 64
#define D  64
#define NVOX (D*D*D)            // 262144
#define NCH  (NB*NC)            // 128
#define TOT  (NCH*NVOX)         // 33554432

#define FIX_T   0.02f
#define MAXFIX  (1<<22)

#define PSTR 65                 // padded smem row stride (float2 elems)
#define ZPB  8                  // z-planes per box_wh block

#define GRID_P 296              // persistent proj blocks (2 per SM)
#define NT     (NB*NVOX/64)     // 8192 voxel tiles of 64

// Scratch (no cudaMalloc allowed)
__device__ float2 g_p [TOT];    // (qk, qkv) bit-exact proj output (fixup source)
__device__ float2 g_t2[TOT];    // after w+h passes
__device__ int    g_cnt;
__device__ int    g_fixlist[MAXFIX];

__global__ void reset_kernel() { g_cnt = 0; }
__global__ void noop_kernel() {}

// ---------------------------------------------------------------------------
// Stage 1: persistent register-tiled projection GEMM, 8l x 4vox per thread.
// Block (128 thr) loads all weights to smem once, loops over 64-voxel tiles.
// Per (l,vox): aqk lanes (aq,ak) = single fma.rn.f32x2 chain over ascending c
// with weights (wq,wk), operand (m,f); av lanes (vox2p, vox2p+1) = chain with
// (wv,wv) and (f,f'). Every lane is an IEEE fp32 FMA -> all chains
// bit-identical to the validated scalar sequential ascending-c chains.
// qk=q*k, qkv=qk*v single roundings; g_p bit-exactness is load-bearing for
// near-zero denominators (fixup). sM/sF separate contiguous arrays ->
// STS.128 commits and 2-wf LDS reads; operand pairs built with mov.b64 on
// the idle ALU pipe. Next tile register-prefetched during compute.
// ---------------------------------------------------------------------------
__global__ __launch_bounds__(128, 2) void proj_kernel(
    const float* __restrict__ mov, const float* __restrict__ fix,
    const float* __restrict__ qw,  const float* __restrict__ kw,
    const float* __restrict__ vw)
{
    extern __shared__ float psm[];
    float2* sWQK = (float2*)psm;              // [c][l] (wq,wk)  32 KB
    float*  sWV  = (float*)(sWQK + NC*NC);    // [c][l] wv       16 KB
    float*  sM   = sWV + NC*NC;               // [c][v] m        16 KB
    float*  sF   = sM + NC*NC;                // [c][v] f        16 KB

    const int tid = threadIdx.x;

    // one-time transposed weight load [l][c] -> [c][l]
    for (int i = tid; i < NC*NC; i += 128) {
        const int c = i >> 6, l = i & 63;
        sWQK[i] = make_float2(qw[l*NC + c], kw[l*NC + c]);
        sWV[i]  = vw[l*NC + c];
    }

    const int l0 = (tid >> 4) << 3;     // 8 l-teams x 8
    const int v0 = (tid & 15) << 2;     // 16 vox-teams x 4

    float4 rm[8], rf[8];
    // preload first tile to regs
    {
        const int t = blockIdx.x;
        const int gv0 = t << 6;
        const int b = (gv0 >= NVOX) ? 1 : 0;
        const int n0 = gv0 & (NVOX - 1);
        const float* bm = mov + (long)b*NC*NVOX + n0;
        const float* bf = fix + (long)b*NC*NVOX + n0;
        #pragma unroll
        for (int k = 0; k < 8; k++) {
            const int idx = tid + (k << 7);
            const int c = idx >> 4, vg = idx & 15;
            rm[k] = *(const float4*)(bm + (long)c*NVOX + vg*4);
            rf[k] = *(const float4*)(bf + (long)c*NVOX + vg*4);
        }
    }
    // commit first tile (contiguous STS.128)
    #pragma unroll
    for (int k = 0; k < 8; k++) {
        const int idx = tid + (k << 7);
        *(float4*)(sM + idx*4) = rm[k];
        *(float4*)(sF + idx*4) = rf[k];
    }
    __syncthreads();

    #pragma unroll 1
    for (int t = blockIdx.x; t < NT; t += GRID_P) {
        const int tn = t + GRID_P;
        // prefetch next tile into regs (overlaps compute)
        if (tn < NT) {
            const int gv0 = tn << 6;
            const int b = (gv0 >= NVOX) ? 1 : 0;
            const int n0 = gv0 & (NVOX - 1);
            const float* bm = mov + (long)b*NC*NVOX + n0;
            const float* bf = fix + (long)b*NC*NVOX + n0;
            #pragma unroll
            for (int k = 0; k < 8; k++) {
                const int idx = tid + (k << 7);
                const int c = idx >> 4, vg = idx & 15;
                rm[k] = *(const float4*)(bm + (long)c*NVOX + vg*4);
                rf[k] = *(const float4*)(bf + (long)c*NVOX + vg*4);
            }
        }

        // ---- compute current tile: 8 l x 4 vox per thread ----
        unsigned long long aqk[8][4];   // lanes (aq, ak)
        unsigned long long av [8][2];   // lanes (av_v2p, av_v2p+1)
        #pragma unroll
        for (int li = 0; li < 8; li++) {
            #pragma unroll
            for (int vi = 0; vi < 4; vi++) aqk[li][vi] = 0ull;
            av[li][0] = 0ull; av[li][1] = 0ull;
        }

        #pragma unroll 2
        for (int c = 0; c < NC; c++) {
            const ulonglong2* wp = (const ulonglong2*)(sWQK + c*NC + l0);
            const ulonglong2 wA = wp[0], wB = wp[1], wC = wp[2], wD = wp[3];
            const unsigned long long wl[8] =
                {wA.x, wA.y, wB.x, wB.y, wC.x, wC.y, wD.x, wD.y};
            const float4 wv0 = *(const float4*)(sWV + c*NC + l0);
            const float4 wv1 = *(const float4*)(sWV + c*NC + l0 + 4);
            unsigned long long vv[8];
            asm("mov.b64 %0, {%1,%1};" : "=l"(vv[0]) : "f"(wv0.x));
            asm("mov.b64 %0, {%1,%1};" : "=l"(vv[1]) : "f"(wv0.y));
            asm("mov.b64 %0, {%1,%1};" : "=l"(vv[2]) : "f"(wv0.z));
            asm("mov.b64 %0, {%1,%1};" : "=l"(vv[3]) : "f"(wv0.w));
            asm("mov.b64 %0, {%1,%1};" : "=l"(vv[4]) : "f"(wv1.x));
            asm("mov.b64 %0, {%1,%1};" : "=l"(vv[5]) : "f"(wv1.y));
            asm("mov.b64 %0, {%1,%1};" : "=l"(vv[6]) : "f"(wv1.z));
            asm("mov.b64 %0, {%1,%1};" : "=l"(vv[7]) : "f"(wv1.w));

            const float4 m4 = *(const float4*)(sM + c*NC + v0);
            const float4 f4 = *(const float4*)(sF + c*NC + v0);
            unsigned long long mf4[4], fp01, fp23;
            asm("mov.b64 %0, {%1,%2};" : "=l"(mf4[0]) : "f"(m4.x), "f"(f4.x));
            asm("mov.b64 %0, {%1,%2};" : "=l"(mf4[1]) : "f"(m4.y), "f"(f4.y));
            asm("mov.b64 %0, {%1,%2};" : "=l"(mf4[2]) : "f"(m4.z), "f"(f4.z));
            asm("mov.b64 %0, {%1,%2};" : "=l"(mf4[3]) : "f"(m4.w), "f"(f4.w));
            asm("mov.b64 %0, {%1,%2};" : "=l"(fp01) : "f"(f4.x), "f"(f4.y));
            asm("mov.b64 %0, {%1,%2};" : "=l"(fp23) : "f"(f4.z), "f"(f4.w));

            #pragma unroll
            for (int li = 0; li < 8; li++) {
                asm("fma.rn.f32x2 %0, %1, %2, %0;" : "+l"(aqk[li][0]) : "l"(wl[li]), "l"(mf4[0]));
                asm("fma.rn.f32x2 %0, %1, %2, %0;" : "+l"(aqk[li][1]) : "l"(wl[li]), "l"(mf4[1]));
                asm("fma.rn.f32x2 %0, %1, %2, %0;" : "+l"(aqk[li][2]) : "l"(wl[li]), "l"(mf4[2]));
                asm("fma.rn.f32x2 %0, %1, %2, %0;" : "+l"(aqk[li][3]) : "l"(wl[li]), "l"(mf4[3]));
                asm("fma.rn.f32x2 %0, %1, %2, %0;" : "+l"(av[li][0]) : "l"(vv[li]), "l"(fp01));
                asm("fma.rn.f32x2 %0, %1, %2, %0;" : "+l"(av[li][1]) : "l"(vv[li]), "l"(fp23));
            }
        }

        // epilogue + store
        {
            const int gv0 = t << 6;
            const int b = (gv0 >= NVOX) ? 1 : 0;
            const int n0 = gv0 & (NVOX - 1);
            #pragma unroll
            for (int li = 0; li < 8; li++) {
                float r[8];
                #pragma unroll
                for (int vi = 0; vi < 4; vi++) {
                    float aq, ak, a0, a1;
                    asm("mov.b64 {%0,%1}, %2;" : "=f"(aq), "=f"(ak) : "l"(aqk[li][vi]));
                    asm("mov.b64 {%0,%1}, %2;" : "=f"(a0), "=f"(a1) : "l"(av[li][vi>>1]));
                    const float avv = (vi & 1) ? a1 : a0;
                    const float qk  = __fmul_rn(aq, ak);
                    const float qkv = __fmul_rn(qk, avv);
                    r[2*vi]   = qk;
                    r[2*vi+1] = qkv;
                }
                float4* po = (float4*)(g_p + (long)b*NC*NVOX + (long)(l0+li)*NVOX + n0 + v0);
                po[0] = make_float4(r[0], r[1], r[2], r[3]);
                po[1] = make_float4(r[4], r[5], r[6], r[7]);
            }
        }
        __syncthreads();     // all smem reads of tile t done

        // commit prefetched tile
        if (tn < NT) {
            #pragma unroll
            for (int k = 0; k < 8; k++) {
                const int idx = tid + (k << 7);
                *(float4*)(sM + idx*4) = rm[k];
                *(float4*)(sF + idx*4) = rf[k];
            }
        }
        __syncthreads();     // next tile ready
    }
}

// ---------------------------------------------------------------------------
// Stage 2ab (fused, software-pipelined): W then H box sums (R9, measured 112us).
// ---------------------------------------------------------------------------
__global__ __launch_bounds__(256) void box_wh_kernel()
{
    extern __shared__ float2 smp[];
    float2* P = smp;               // [64][PSTR] current input plane
    float2* Q = smp + D*PSTR;      // [64][PSTR] after w-pass

    const int tid  = threadIdx.x;
    const int z0   = blockIdx.x * ZPB;
    const int chan = blockIdx.y;
    const long cb  = (long)chan*NVOX;

    for (int i = tid; i < D*D; i += 256)
        P[(i >> 6)*PSTR + (i & 63)] = g_p[cb + (long)z0*(D*D) + i];
    __syncthreads();

    #pragma unroll 1
    for (int p = 0; p < ZPB; p++) {
        const long nb = cb + (long)(z0 + p + 1)*(D*D);
        const bool pf = (p + 1 < ZPB);
        float2 rA[8], rB[8];

        if (pf) {
            #pragma unroll
            for (int k = 0; k < 8; k++) rA[k] = g_p[nb + k*256 + tid];
        }

        // w-pass: P -> Q
        {
            const int h   = tid & 63;
            const int w0  = (tid >> 6) * 16;
            const float2* row = P + h*PSTR;
            float2* qrow = Q + h*PSTR;
            float sx = 0.f, sy = 0.f;
            const int j0 = (w0 >= 4) ? (w0 - 4) : 0;
            for (int j = j0; j < w0 + 4; j++) { sx += row[j].x; sy += row[j].y; }
            #pragma unroll
            for (int i = 0; i < 16; i++) {
                const int w = w0 + i;
                if (w + 4 < D) { sx += row[w+4].x; sy += row[w+4].y; }
                qrow[w] = make_float2(sx, sy);
                if (w >= 4) { sx -= row[w-4].x; sy -= row[w-4].y; }
            }
        }
        __syncthreads();

        if (pf) {
            #pragma unroll
            for (int k = 0; k < 8; k++) rB[k] = g_p[nb + (k+8)*256 + tid];
        }

        // h-pass: Q -> g_t2
        {
            const int w   = tid & 63;
            const int h0  = (tid >> 6) * 16;
            const long pbase = cb + (long)(z0 + p)*(D*D);
            float sx = 0.f, sy = 0.f;
            const int j0 = (h0 >= 4) ? (h0 - 4) : 0;
            for (int j = j0; j < h0 + 4; j++) {
                const float2 v = Q[j*PSTR + w];
                sx += v.x; sy += v.y;
            }
            #pragma unroll
            for (int i = 0; i < 16; i++) {
                const int h = h0 + i;
                if (h + 4 < D) {
                    const float2 v = Q[(h+4)*PSTR + w];
                    sx += v.x; sy += v.y;
                }
                g_t2[pbase + h*D + w] = make_float2(sx, sy);
                if (h >= 4) {
                    const float2 v = Q[(h-4)*PSTR + w];
                    sx -= v.x; sy -= v.y;
                }
            }
        }

        if (pf) {
            #pragma unroll
            for (int k = 0; k < 8; k++) {
                const int i = k*256 + tid;
                P[(i >> 6)*PSTR + (i & 63)] = rA[k];
            }
            #pragma unroll
            for (int k = 0; k < 8; k++) {
                const int i = (k+8)*256 + tid;
                P[(i >> 6)*PSTR + (i & 63)] = rB[k];
            }
        }
        __syncthreads();
    }
}

// ---------------------------------------------------------------------------
// Stage 2c: box sum along Z + division; flag near-zero denominators.
// ---------------------------------------------------------------------------
__global__ __launch_bounds__(256) void box_z_div_kernel(float* __restrict__ out)
{
    const int t    = threadIdx.x;
    const int wp   = t & 31;
    const int h    = blockIdx.x * 8 + (t >> 5);
    const int chan = blockIdx.y;
    const long ebase = (long)chan*NVOX + (long)h*D + 2*wp;
    const long base  = ebase >> 1;
    const float4* src = (const float4*)g_t2;
    float2*       o2  = (float2*)out;

    float4 ring[9];
    float4 s = make_float4(0.f, 0.f, 0.f, 0.f);
    #pragma unroll
    for (int j = 0; j < 4; j++) {
        float4 v = src[base + (long)j*(D*D/2)];
        ring[j % 9] = v;
        s.x += v.x; s.y += v.y; s.z += v.z; s.w += v.w;
    }
    #pragma unroll
    for (int i = 0; i < D; i++) {
        const int j = i + 4;
        if (j < D) {
            float4 v = src[base + (long)j*(D*D/2)];
            ring[j % 9] = v;
            s.x += v.x; s.y += v.y; s.z += v.z; s.w += v.w;
        }
        const long eidx = ebase + (long)i*(D*D);
        o2[eidx >> 1] = make_float2(__fdiv_rn(s.y, s.x), __fdiv_rn(s.w, s.z));
        if (fabsf(s.x) < FIX_T) {
            int slot = atomicAdd(&g_cnt, 1);
            if (slot < MAXFIX) g_fixlist[slot] = (int)eidx;
        }
        if (fabsf(s.z) < FIX_T) {
            int slot = atomicAdd(&g_cnt, 1);
            if (slot < MAXFIX) g_fixlist[slot] = (int)(eidx + 1);
        }
        const int j2 = i - 4;
        if (j2 >= 0) {
            float4 v = ring[j2 % 9];
            s.x -= v.x; s.y -= v.y; s.z -= v.z; s.w -= v.w;
        }
    }
}

// ---------------------------------------------------------------------------
// Stage 3: exact fixup — reference's sequential in-bounds 729-tap fold
// (ascending z,h,w; fp32 adds; init 0) over the bit-exact g_p field.
// ---------------------------------------------------------------------------
__global__ __launch_bounds__(256) void fixup_kernel(float* __restrict__ out)
{
    int cnt = g_cnt; if (cnt > MAXFIX) cnt = MAXFIX;
    for (int idx = blockIdx.x*256 + threadIdx.x; idx < cnt; idx += gridDim.x*256) {
        const int v    = g_fixlist[idx];
        const int chan = v >> 18;
        const int rem  = v & (NVOX-1);
        const int z = rem >> 12;
        const int h = (rem >> 6) & 63;
        const int w = rem & 63;
        const long cb = (long)chan*NVOX;

        const int zlo = z-4 < 0 ? 0 : z-4, zhi = z+4 > 63 ? 63 : z+4;
        const int hlo = h-4 < 0 ? 0 : h-4, hhi = h+4 > 63 ? 63 : h+4;
        const int wlo = w-4 < 0 ? 0 : w-4, whi = w+4 > 63 ? 63 : w+4;

        float sD = 0.f, sN = 0.f;
        for (int dz = zlo; dz <= zhi; dz++)
            for (int dh = hlo; dh <= hhi; dh++) {
                const float2* row = g_p + cb + ((long)dz*D + dh)*D;
                for (int dw = wlo; dw <= whi; dw++) {
                    float2 x = row[dw];
                    sD = __fadd_rn(sD, x.x);
                    sN = __fadd_rn(sN, x.y);
                }
            }
        out[v] = __fdiv_rn(sN, sD);
    }
}

extern "C" void kernel_launch(void* const* d_in, const int* in_sizes, int n_in,
                              void* d_out, int out_size) {
    (void)in_sizes; (void)n_in; (void)out_size;
    const float* mov = (const float*)d_in[0];
    const float* fix = (const float*)d_in[1];
    const float* qw  = (const float*)d_in[2];
    const float* kw  = (const float*)d_in[3];
    const float* vw  = (const float*)d_in[4];
    float* out = (float*)d_out;

    const int proj_smem = 81920;                        // 80 KB
    const int wh_smem   = 2*D*PSTR * sizeof(float2);    // 66560 B
    cudaFuncSetAttribute(proj_kernel,
                         cudaFuncAttributeMaxDynamicSharedMemorySize, proj_smem);
    cudaFuncSetAttribute(box_wh_kernel,
                         cudaFuncAttributeMaxDynamicSharedMemorySize, wh_smem);

    reset_kernel<<<1, 1>>>();                           // 0
    noop_kernel<<<1, 32>>>();                           // 1
    noop_kernel<<<1, 32>>>();                           // 2
    proj_kernel<<<GRID_P, 128, proj_smem>>>(mov, fix, qw, kw, vw);   // 3 (captured)
    box_wh_kernel<<<dim3(D/ZPB, NCH), 256, wh_smem>>>();
    box_z_div_kernel<<<dim3(8, NCH), 256>>>(out);
    fixup_kernel<<<512, 256>>>(out);
}